// round 8
// baseline (speedup 1.0000x reference)
#include <cuda_runtime.h>
#include <cuda_fp16.h>
#include <cstdint>

namespace {
constexpr int B = 16;
constexpr int L = 1024;
constexpr int H = 512;
constexpr int V = 32000;
constexpr int HALF = 256;
constexpr int TOK = B * L;           // 16384
constexpr float ALPHA_C = 0.05f;     // 1 - 0.95
constexpr float EPS_LN_C = 1e-5f;
constexpr float EPS_NORM_C = 1e-12f;

// GEMM tiling (fp16 operands, fp32 accum)
constexpr int TM = 128;
constexpr int TN = 128;
constexpr int TKH = 64;              // halves per k-tile = 128 bytes per row
constexpr int STG = 3;               // cp.async stages
constexpr int TILE_BYTES = 128 * 128;            // 16 KB per matrix per stage
constexpr int SMEM_H = STG * 2 * TILE_BYTES;     // 96 KB
}

// ---------------- scratch (static device globals; no allocation) ----------------
__device__ __half g_h0h[TOK * H];            // embed gather output (fp16)
__device__ __half g_ff1h[TOK * 2 * H];       // FFN hidden (fp16)
__device__ float  g_y2[TOK * H];             // FFN output (pre-LN, fp32)
__device__ __half g_hh[TOK * H];             // post-LN hidden (fp16)
__device__ float  g_kn[2 * L * B * HALF];    // RAW keys [m][l][b][i]
__device__ float  g_c[B * H];                // context
__device__ float  g_r[B * H];                // readout projection
__device__ __half g_w1h[2 * H * H];          // fp16 ff_w1
__device__ __half g_w2h[2 * H * H];          // fp16 ff_w2
__device__ __half g_wch[2 * HALF * H];       // fp16 [sem_w ; epi_w]

// ---------------- helpers ----------------
__device__ __forceinline__ uint32_t smem_u32(const void* p) {
    return (uint32_t)__cvta_generic_to_shared(p);
}
__device__ __forceinline__ void cp16(uint32_t dst, const void* src) {
    asm volatile("cp.async.cg.shared.global [%0], [%1], 16;" :: "r"(dst), "l"(src));
}
__device__ __forceinline__ uint32_t sw128(uint32_t off) {
    return off ^ ((off >> 3) & 0x70u);
}
__device__ __forceinline__ void ldsm_x4(uint32_t& r0, uint32_t& r1, uint32_t& r2,
                                        uint32_t& r3, uint32_t a) {
    asm volatile("ldmatrix.sync.aligned.m8n8.x4.shared.b16 {%0,%1,%2,%3}, [%4];"
                 : "=r"(r0), "=r"(r1), "=r"(r2), "=r"(r3) : "r"(a));
}
__device__ __forceinline__ void mma_f16(float* d, const uint32_t* a, const uint32_t* b) {
    asm volatile(
        "mma.sync.aligned.m16n8k16.row.col.f32.f16.f16.f32 "
        "{%0,%1,%2,%3},{%4,%5,%6,%7},{%8,%9},{%0,%1,%2,%3};"
        : "+f"(d[0]), "+f"(d[1]), "+f"(d[2]), "+f"(d[3])
        : "r"(a[0]), "r"(a[1]), "r"(a[2]), "r"(a[3]), "r"(b[0]), "r"(b[1]));
}

// ---------------- merged fp32 -> fp16 weight conversion ----------------
// blocks [0,512): ff_w1 ; [512,1024): ff_w2 ; [1024,1152): sem ; [1152,1280): epi
__global__ void k_round_all(const float* __restrict__ w1, const float* __restrict__ w2,
                            const float* __restrict__ sem, const float* __restrict__ epi,
                            __half* __restrict__ d1, __half* __restrict__ d2,
                            __half* __restrict__ dc) {
    int blk = blockIdx.x;
    const float* src;
    __half* dst;
    int base;
    if (blk < 512)       { src = w1;  dst = d1; base = blk; }
    else if (blk < 1024) { src = w2;  dst = d2; base = blk - 512; }
    else if (blk < 1152) { src = sem; dst = dc; base = blk - 1024; }
    else                 { src = epi; dst = dc + (size_t)HALF * H; base = blk - 1152; }
    int i = base * 256 + threadIdx.x;
    float4 v = __ldg(reinterpret_cast<const float4*>(src) + i);
    __half2* d = reinterpret_cast<__half2*>(dst) + i * 2;
    d[0] = __floats2half2_rn(v.x, v.y);
    d[1] = __floats2half2_rn(v.z, v.w);
}

// ---------------- embedding gather (fp16 out) ----------------
__global__ void k_gather(const int* __restrict__ seq, const float* __restrict__ embed,
                         __half* __restrict__ out) {
    int t = blockIdx.x;
    int v = seq[t];
    const float4* src = reinterpret_cast<const float4*>(embed + (size_t)v * H);
    float4 x = src[threadIdx.x];
    __half2* dst = reinterpret_cast<__half2*>(out + (size_t)t * H) + threadIdx.x * 2;
    dst[0] = __floats2half2_rn(x.x, x.y);
    dst[1] = __floats2half2_rn(x.z, x.w);
}

// ---------------- fp16 tensor GEMM: C[m,n] = A[m,:] . W[n,:] ----------------
// 128x128 CTA tile, BK=64 halves (SW128), 3-stage cp.async, 8 warps 2x4,
// 64x32 warp tiles, fp32 accum. B fragments loaded as paired ldmatrix.x4.
// MODE 0: +bias -> fp32; MODE 1: +bias+relu -> fp16; MODE 2: raw scatter [m][l][b][c]
template <int MODE>
__global__ void __launch_bounds__(256) k_gemm(const __half* __restrict__ A,
                                              const __half* __restrict__ W,
                                              const float* __restrict__ bias,
                                              void* __restrict__ Cv,
                                              int N, int K) {
    extern __shared__ char smem[];
    const uint32_t sb = smem_u32(smem);
    uint32_t a_off[STG], w_off[STG];
#pragma unroll
    for (int s = 0; s < STG; ++s) {
        a_off[s] = s * 2 * TILE_BYTES;
        w_off[s] = s * 2 * TILE_BYTES + TILE_BYTES;
    }

    const int tid = threadIdx.x;
    const int bm = blockIdx.y * TM;
    const int bn = blockIdx.x * TN;
    const int warp = tid >> 5, lane = tid & 31;
    const int wm = warp >> 2, wn = warp & 3;   // 2 x 4 warp grid
    const int g = lane >> 2, tg = lane & 3;

    // global loader: 256 threads cover 128 rows x 128B per matrix (4 x 16B each)
    const int row = tid >> 1;
    const int h64 = tid & 1;
    const __half* Ag = A + (size_t)(bm + row) * K + h64 * 32;
    const __half* Wg = W + (size_t)(bn + row) * K + h64 * 32;
    uint32_t swz[4];
#pragma unroll
    for (int c = 0; c < 4; ++c) swz[c] = sw128(row * 128 + h64 * 64 + c * 16);

    float acc[4][4][4];
#pragma unroll
    for (int mi = 0; mi < 4; ++mi)
#pragma unroll
        for (int ni = 0; ni < 4; ++ni)
#pragma unroll
            for (int q = 0; q < 4; ++q) acc[mi][ni][q] = 0.f;

    auto issue_tile = [&](int st, int kt) {
#pragma unroll
        for (int c = 0; c < 4; ++c)
            cp16(sb + a_off[st] + swz[c], Ag + (size_t)kt * TKH + c * 8);
#pragma unroll
        for (int c = 0; c < 4; ++c)
            cp16(sb + w_off[st] + swz[c], Wg + (size_t)kt * TKH + c * 8);
        asm volatile("cp.async.commit_group;" ::: "memory");
    };

    // ldsm lane addressing
    const int a_r = lane & 15;                      // A: row within m16
    const int a_cb = (lane >> 4) * 16;              // A: k-half byte offset
    const int b_r = ((lane >> 4) << 3) + (lane & 7);   // B: row within ni-pair (16 rows)
    const int b_cb = ((lane >> 3) & 1) * 16;        // B: k-half byte offset

    auto mma_pass = [&](int buf) {
#pragma unroll
        for (int ak = 0; ak < 4; ++ak) {
            const int kb = ak * 32;                 // 16 halves = 32 bytes
            uint32_t afrag[4][4];
#pragma unroll
            for (int mi = 0; mi < 4; ++mi) {
                uint32_t addr = sb + a_off[buf] +
                    sw128((uint32_t)(wm * 64 + mi * 16 + a_r) * 128 + kb + a_cb);
                ldsm_x4(afrag[mi][0], afrag[mi][1], afrag[mi][2], afrag[mi][3], addr);
            }
            uint32_t bfrag[4][2];
#pragma unroll
            for (int nip = 0; nip < 2; ++nip) {
                uint32_t addr = sb + w_off[buf] +
                    sw128((uint32_t)(wn * 32 + nip * 16 + b_r) * 128 + kb + b_cb);
                ldsm_x4(bfrag[nip * 2][0], bfrag[nip * 2][1],
                        bfrag[nip * 2 + 1][0], bfrag[nip * 2 + 1][1], addr);
            }
#pragma unroll
            for (int mi = 0; mi < 4; ++mi)
#pragma unroll
                for (int ni = 0; ni < 4; ++ni)
                    mma_f16(acc[mi][ni], afrag[mi], bfrag[ni]);
        }
    };

    const int NPASS = K / TKH;
    issue_tile(0, 0);
    issue_tile(1, 1);

    int p = 0;
    for (; p < NPASS - 1; ++p) {
        asm volatile("cp.async.wait_group 1;" ::: "memory");
        __syncthreads();
        if (p + 2 < NPASS) issue_tile((p + 2) % STG, p + 2);
        mma_pass(p % STG);
    }
    asm volatile("cp.async.wait_group 0;" ::: "memory");
    __syncthreads();
    mma_pass(p % STG);

    // epilogue: acc reg q -> row g + (q>=2)*8, col tg*2 + (q&1)
#pragma unroll
    for (int mi = 0; mi < 4; ++mi) {
#pragma unroll
        for (int half = 0; half < 2; ++half) {
            int r = bm + wm * 64 + mi * 16 + g + half * 8;
#pragma unroll
            for (int ni = 0; ni < 4; ++ni) {
                int col = bn + wn * 32 + ni * 8 + tg * 2;
                float x = acc[mi][ni][half * 2 + 0];
                float y = acc[mi][ni][half * 2 + 1];
                if (MODE == 2) {
                    int b_ = r >> 10, l_ = r & 1023;
                    int m_ = col >> 8, c_ = col & 255;
                    float* dst = (float*)Cv + (size_t)m_ * (L * B * HALF) +
                                 ((size_t)l_ * B + b_) * HALF + c_;
                    *reinterpret_cast<float2*>(dst) = make_float2(x, y);
                } else if (MODE == 0) {
                    x += bias[col];
                    y += bias[col + 1];
                    float* dst = (float*)Cv + (size_t)r * N + col;
                    *reinterpret_cast<float2*>(dst) = make_float2(x, y);
                } else {
                    x = fmaxf(x + bias[col], 0.f);
                    y = fmaxf(y + bias[col + 1], 0.f);
                    __half* dst = (__half*)Cv + (size_t)r * N + col;
                    *reinterpret_cast<__half2*>(dst) = __floats2half2_rn(x, y);
                }
            }
        }
    }
}

// ---------------- residual + LayerNorm (warp per row; fp16 out) ----------------
__global__ void k_ln(const float* __restrict__ y2, const __half* __restrict__ h0,
                     const float* __restrict__ gamma, const float* __restrict__ beta,
                     __half* __restrict__ out) {
    int warp = threadIdx.x >> 5, lane = threadIdx.x & 31;
    int row = blockIdx.x * 8 + warp;
    const float4* a = reinterpret_cast<const float4*>(y2 + (size_t)row * H);
    const __half2* hb = reinterpret_cast<const __half2*>(h0 + (size_t)row * H);
    float x[16];
    float s = 0.f, s2 = 0.f;
#pragma unroll
    for (int i = 0; i < 4; ++i) {
        float4 u = a[lane + i * 32];
        float2 v0 = __half22float2(hb[(lane + i * 32) * 2]);
        float2 v1 = __half22float2(hb[(lane + i * 32) * 2 + 1]);
        float t0 = u.x + v0.x, t1 = u.y + v0.y, t2 = u.z + v1.x, t3 = u.w + v1.y;
        x[i * 4 + 0] = t0; x[i * 4 + 1] = t1; x[i * 4 + 2] = t2; x[i * 4 + 3] = t3;
        s += t0 + t1 + t2 + t3;
        s2 += t0 * t0 + t1 * t1 + t2 * t2 + t3 * t3;
    }
#pragma unroll
    for (int off = 16; off > 0; off >>= 1) {
        s += __shfl_xor_sync(0xffffffffu, s, off);
        s2 += __shfl_xor_sync(0xffffffffu, s2, off);
    }
    float mu = s * (1.f / H);
    float var = s2 * (1.f / H) - mu * mu;
    float rstd = rsqrtf(var + EPS_LN_C);
    __half2* o = reinterpret_cast<__half2*>(out + (size_t)row * H);
    const float4* g4 = reinterpret_cast<const float4*>(gamma);
    const float4* b4 = reinterpret_cast<const float4*>(beta);
#pragma unroll
    for (int i = 0; i < 4; ++i) {
        float4 gg = __ldg(g4 + lane + i * 32);
        float4 bb = __ldg(b4 + lane + i * 32);
        float r0 = (x[i * 4 + 0] - mu) * rstd * gg.x + bb.x;
        float r1 = (x[i * 4 + 1] - mu) * rstd * gg.y + bb.y;
        float r2 = (x[i * 4 + 2] - mu) * rstd * gg.z + bb.z;
        float r3 = (x[i * 4 + 3] - mu) * rstd * gg.w + bb.w;
        o[(lane + i * 32) * 2] = __floats2half2_rn(r0, r1);
        o[(lane + i * 32) * 2 + 1] = __floats2half2_rn(r2, r3);
    }
}

// ---------------- EMA scan on RAW keys (normalization fused) ----------------
// For each block of 4 steps: 14 warp-reduced dots (u_j = r_j.v, 6 Gram pairs,
// 4 self-dots). Normalization folded into scalar recurrence.
__device__ __forceinline__ void scan_load4(const float* kn, int t0, int lane,
                                           float k4[4][8]) {
    const int STRD = B * HALF;
#pragma unroll
    for (int j = 0; j < 4; ++j) {
        const float4* p = reinterpret_cast<const float4*>(kn + (size_t)(t0 + j) * STRD + lane * 8);
        float4 u = __ldg(p), w = __ldg(p + 1);
        k4[j][0] = u.x; k4[j][1] = u.y; k4[j][2] = u.z; k4[j][3] = u.w;
        k4[j][4] = w.x; k4[j][5] = w.y; k4[j][6] = w.z; k4[j][7] = w.w;
    }
}

__device__ __forceinline__ void scan_step4(const float cur[4][8],
                                           float v[8], float cac[8]) {
    float red[14];
#pragma unroll
    for (int q = 0; q < 14; ++q) red[q] = 0.f;
#pragma unroll
    for (int j = 0; j < 8; ++j) {
        float vj = v[j];
        float k0 = cur[0][j], k1 = cur[1][j], k2 = cur[2][j], k3 = cur[3][j];
        red[0] += k0 * vj;
        red[1] += k1 * vj;
        red[2] += k2 * vj;
        red[3] += k3 * vj;
        red[4] += k3 * k2;
        red[5] += k3 * k1;
        red[6] += k3 * k0;
        red[7] += k2 * k1;
        red[8] += k2 * k0;
        red[9] += k1 * k0;
        red[10] += k0 * k0;
        red[11] += k1 * k1;
        red[12] += k2 * k2;
        red[13] += k3 * k3;
    }
#pragma unroll
    for (int off = 16; off > 0; off >>= 1)
#pragma unroll
        for (int q = 0; q < 14; ++q)
            red[q] += __shfl_xor_sync(0xffffffffu, red[q], off);

    float i0 = 1.f / fmaxf(sqrtf(red[10]), EPS_NORM_C);
    float i1 = 1.f / fmaxf(sqrtf(red[11]), EPS_NORM_C);
    float i2 = 1.f / fmaxf(sqrtf(red[12]), EPS_NORM_C);
    float i3 = 1.f / fmaxf(sqrtf(red[13]), EPS_NORM_C);

    // s_j = kn_j . v_partial (normalized-key dot), computed via raw dots
    float s3 = red[3] * i3;
    float s2 = red[2] * i2 - ALPHA_C * (red[4] * i2 * i3) * s3;
    float s1 = red[1] * i1 - ALPHA_C * ((red[5] * i1 * i3) * s3 + (red[7] * i1 * i2) * s2);
    float s0 = red[0] * i0 - ALPHA_C * ((red[6] * i0 * i3) * s3 + (red[8] * i0 * i2) * s2 +
                                        (red[9] * i0 * i1) * s1);
    // v -= alpha * sum kn_j s_j = alpha * (i_j s_j) r_j ; cac += r_j s_j
    float a3 = ALPHA_C * i3 * s3, a2 = ALPHA_C * i2 * s2;
    float a1 = ALPHA_C * i1 * s1, a0 = ALPHA_C * i0 * s0;
#pragma unroll
    for (int j = 0; j < 8; ++j) {
        float k0 = cur[0][j], k1 = cur[1][j], k2 = cur[2][j], k3 = cur[3][j];
        v[j] -= k3 * a3 + k2 * a2 + k1 * a1 + k0 * a0;
        cac[j] += k3 * s3 + k2 * s2 + k1 * s1 + k0 * s0;
    }
}

__global__ void __launch_bounds__(32) k_scan(const float* __restrict__ kn_all,
                                             float* __restrict__ cbuf) {
    const int lane = threadIdx.x;
    const int m = blockIdx.x >> 4;
    const int b = blockIdx.x & 15;
    const float* kn = kn_all + (size_t)m * L * B * HALF + b * HALF;
    const int STRD = B * HALF;

    float v[8], cac[8];
    {   // v starts at the raw (unnormalized) final query
        const float4* p = reinterpret_cast<const float4*>(kn + (size_t)(L - 1) * STRD + lane * 8);
        float4 u = __ldg(p), w = __ldg(p + 1);
        v[0] = u.x; v[1] = u.y; v[2] = u.z; v[3] = u.w;
        v[4] = w.x; v[5] = w.y; v[6] = w.z; v[7] = w.w;
    }
#pragma unroll
    for (int j = 0; j < 8; ++j) cac[j] = 0.f;

    float bA[4][8], bB[4][8], bC[4][8];
    scan_load4(kn, L - 5, lane, bA);    // t0 = 1019
    scan_load4(kn, L - 9, lane, bB);    // t0 = 1015

    int t0 = L - 5;
    for (int it = 0; it < 85; ++it) {
        if (t0 >= 11) scan_load4(kn, t0 - 8, lane, bC);
        scan_step4(bA, v, cac);
        t0 -= 4;
        if (t0 >= 11) scan_load4(kn, t0 - 8, lane, bA);
        scan_step4(bB, v, cac);
        t0 -= 4;
        if (t0 >= 11) scan_load4(kn, t0 - 8, lane, bB);
        scan_step4(bC, v, cac);
        t0 -= 4;
    }

    // remainder: t = 2, 1, 0 single steps
    for (int t = 2; t >= 0; --t) {
        float kt[8];
        const float4* p = reinterpret_cast<const float4*>(kn + (size_t)t * STRD + lane * 8);
        float4 u = __ldg(p), w = __ldg(p + 1);
        kt[0] = u.x; kt[1] = u.y; kt[2] = u.z; kt[3] = u.w;
        kt[4] = w.x; kt[5] = w.y; kt[6] = w.z; kt[7] = w.w;
        float du = 0.f, dg = 0.f;
#pragma unroll
        for (int j = 0; j < 8; ++j) { du += kt[j] * v[j]; dg += kt[j] * kt[j]; }
#pragma unroll
        for (int off = 16; off > 0; off >>= 1) {
            du += __shfl_xor_sync(0xffffffffu, du, off);
            dg += __shfl_xor_sync(0xffffffffu, dg, off);
        }
        float inv = 1.f / fmaxf(sqrtf(dg), EPS_NORM_C);
        float s = du * inv;            // kn . v
        float av = ALPHA_C * inv * s;
#pragma unroll
        for (int j = 0; j < 8; ++j) {
            cac[j] += kt[j] * s;
            v[j] -= kt[j] * av;
        }
    }

    float* out = cbuf + b * H + m * HALF + lane * 8;
#pragma unroll
    for (int j = 0; j < 8; ++j) out[j] = ALPHA_C * cac[j];
}

// ---------------- r = c @ rp_w^T + rp_b ----------------
__global__ void k_rp(const float* __restrict__ c, const float* __restrict__ W,
                     const float* __restrict__ bias, float* __restrict__ r) {
    __shared__ float cs[B * (H + 1)];
    for (int i = threadIdx.x; i < B * H; i += 256) {
        int bb = i >> 9, hh = i & 511;
        cs[bb * (H + 1) + hh] = c[i];
    }
    __syncthreads();
    int g = blockIdx.x * 16 + (threadIdx.x >> 4);
    int b = threadIdx.x & 15;
    const float* w = W + (size_t)g * H;
    const float* cb = &cs[b * (H + 1)];
    float acc = 0.f;
    for (int h = 0; h < H; h += 4) {
        float4 wv = __ldg(reinterpret_cast<const float4*>(w + h));
        acc += cb[h] * wv.x + cb[h + 1] * wv.y + cb[h + 2] * wv.z + cb[h + 3] * wv.w;
    }
    r[b * H + g] = acc + bias[g];
}

// ---------------- out = r @ out_w^T + out_b ----------------
__global__ void k_out(const float* __restrict__ r, const float* __restrict__ W,
                      const float* __restrict__ bias, float* __restrict__ out) {
    __shared__ float rs[B * H];
    for (int i = threadIdx.x; i < B * H; i += 256) rs[i] = r[i];
    __syncthreads();
    int v = blockIdx.x * 256 + threadIdx.x;
    float acc[B];
#pragma unroll
    for (int b = 0; b < B; ++b) acc[b] = 0.f;
    const float4* w = reinterpret_cast<const float4*>(W + (size_t)v * H);
#pragma unroll 4
    for (int i = 0; i < H / 4; ++i) {
        float4 wv = __ldg(w + i);
#pragma unroll
        for (int b = 0; b < B; ++b) {
            float4 rv = *reinterpret_cast<const float4*>(&rs[b * H + i * 4]);
            acc[b] += rv.x * wv.x + rv.y * wv.y + rv.z * wv.z + rv.w * wv.w;
        }
    }
    float bb = __ldg(bias + v);
#pragma unroll
    for (int b = 0; b < B; ++b) out[(size_t)b * V + v] = acc[b] + bb;
}

// ---------------- launch ----------------
extern "C" void kernel_launch(void* const* d_in, const int* in_sizes, int n_in,
                              void* d_out, int out_size) {
    const int*   seq   = (const int*)d_in[0];
    const float* embed = (const float*)d_in[1];
    const float* ff_w1 = (const float*)d_in[2];
    const float* ff_b1 = (const float*)d_in[3];
    const float* ff_w2 = (const float*)d_in[4];
    const float* ff_b2 = (const float*)d_in[5];
    const float* gamma = (const float*)d_in[6];
    const float* beta  = (const float*)d_in[7];
    const float* sem_w = (const float*)d_in[8];
    const float* epi_w = (const float*)d_in[9];
    const float* rp_w  = (const float*)d_in[10];
    const float* rp_b  = (const float*)d_in[11];
    const float* out_w = (const float*)d_in[12];
    const float* out_b = (const float*)d_in[13];
    float* out = (float*)d_out;

    __half *h0h, *ff1h, *hh, *w1h, *w2h, *wch;
    float *y2, *kn, *c, *r;
    cudaGetSymbolAddress((void**)&h0h,  g_h0h);
    cudaGetSymbolAddress((void**)&ff1h, g_ff1h);
    cudaGetSymbolAddress((void**)&y2,   g_y2);
    cudaGetSymbolAddress((void**)&hh,   g_hh);
    cudaGetSymbolAddress((void**)&kn,   g_kn);
    cudaGetSymbolAddress((void**)&c,    g_c);
    cudaGetSymbolAddress((void**)&r,    g_r);
    cudaGetSymbolAddress((void**)&w1h,  g_w1h);
    cudaGetSymbolAddress((void**)&w2h,  g_w2h);
    cudaGetSymbolAddress((void**)&wch,  g_wch);

    cudaFuncSetAttribute(k_gemm<0>, cudaFuncAttributeMaxDynamicSharedMemorySize, SMEM_H);
    cudaFuncSetAttribute(k_gemm<1>, cudaFuncAttributeMaxDynamicSharedMemorySize, SMEM_H);
    cudaFuncSetAttribute(k_gemm<2>, cudaFuncAttributeMaxDynamicSharedMemorySize, SMEM_H);

    // 0. convert all weights to fp16 in one launch
    k_round_all<<<1280, 256>>>(ff_w1, ff_w2, sem_w, epi_w, w1h, w2h, wch);
    // 1. embedding gather (fp16)
    k_gather<<<TOK, 128>>>(seq, embed, h0h);
    // 2. FFN up (relu, fp16 out)   [16384 x 1024 x 512]
    k_gemm<1><<<dim3(2 * H / TN, TOK / TM), 256, SMEM_H>>>(h0h, w1h, ff_b1, ff1h, 2 * H, H);
    // 3. FFN down (fp32 out)       [16384 x 512 x 1024]
    k_gemm<0><<<dim3(H / TN, TOK / TM), 256, SMEM_H>>>(ff1h, w2h, ff_b2, y2, H, 2 * H);
    // 4. residual + layernorm (fp16 out)
    k_ln<<<TOK / 8, 256>>>(y2, h0h, gamma, beta, hh);
    // 5. merged key projections (N=512), RAW keys scattered to kn[m][l][b][c]
    k_gemm<2><<<dim3(2 * HALF / TN, TOK / TM), 256, SMEM_H>>>(hh, wch, nullptr, kn, 2 * HALF, H);
    // 6. backward-query scan with fused normalization
    k_scan<<<32, 32>>>(kn, c);
    // 7. readout projection
    k_rp<<<H / 16, 256>>>(c, rp_w, rp_b, r);
    // 8. logits
    k_out<<<V / 256, 256>>>(r, out_w, out_b, out);
}